// round 15
// baseline (speedup 1.0000x reference)
#include <cuda_runtime.h>
#include <math.h>

#define NPTS 8192
#define CF   64
#define NH   4
#define KNN  16
#define DHD  16
#define PPB  2

#define GRES 16
#define GC   (GRES * GRES * GRES)

#define FINF 3.402823466e38f
#define FULLM 0xffffffffu

#define PACK2(out, lo, hi) \
    asm("mov.b64 %0, {%1, %2};" : "=l"(out) : "r"(lo), "r"(hi))
#define UNPACK2(lo, hi, in) \
    asm("mov.b64 {%0, %1}, %2;" : "=r"(lo), "=r"(hi) : "l"(in))
#define FMA2(d, a, b, c) \
    asm("fma.rn.f32x2 %0, %1, %2, %3;" : "=l"(d) : "l"(a), "l"(b), "l"(c))

// ---------------- scratch (static device memory; no allocations) -------------
__device__ float g_xq[NPTS * CF];
__device__ float g_xk[NPTS * CF];
__device__ float g_xv[NPTS * CF];
__device__ int   g_idx[NPTS * KNN];

__device__ unsigned g_bbmin[3];
__device__ unsigned g_bbmax[3];
__device__ int      g_cellcnt[GC];
__device__ int      g_cellstart[GC];
__device__ int      g_cellcur[GC];
__device__ __align__(16) float4 g_ps4[NPTS];
__device__ int      g_pidn[NPTS];

// ---------------- float <-> ordered-uint encode for atomic min/max ----------
__device__ __forceinline__ unsigned fenc(float f) {
    unsigned u = __float_as_uint(f);
    return (u & 0x80000000u) ? ~u : (u | 0x80000000u);
}
__device__ __forceinline__ float fdec(unsigned e) {
    unsigned u = (e & 0x80000000u) ? (e & 0x7FFFFFFFu) : ~e;
    return __uint_as_float(u);
}
__device__ __forceinline__ int cell1(float v, float lo, float inv) {
    int c = (int)((v - lo) * inv);
    return min(GRES - 1, max(0, c));
}

// ---------------- grid build ------------------------------------------------
__global__ void grid_init_kernel() {
    const int idx = blockIdx.x * 1024 + threadIdx.x;
    if (idx < GC) g_cellcnt[idx] = 0;
    if (blockIdx.x == 0 && threadIdx.x < 3) {
        g_bbmin[threadIdx.x] = 0xFFFFFFFFu;
        g_bbmax[threadIdx.x] = 0u;
    }
}

__global__ void __launch_bounds__(256)
bbox_kernel(const float* __restrict__ p) {
    const int tid = blockIdx.x * 256 + threadIdx.x;
    float x = p[3 * tid + 0], y = p[3 * tid + 1], z = p[3 * tid + 2];
    float mnx = x, mxx = x, mny = y, mxy = y, mnz = z, mxz = z;
#pragma unroll
    for (int s = 16; s >= 1; s >>= 1) {
        mnx = fminf(mnx, __shfl_xor_sync(FULLM, mnx, s));
        mxx = fmaxf(mxx, __shfl_xor_sync(FULLM, mxx, s));
        mny = fminf(mny, __shfl_xor_sync(FULLM, mny, s));
        mxy = fmaxf(mxy, __shfl_xor_sync(FULLM, mxy, s));
        mnz = fminf(mnz, __shfl_xor_sync(FULLM, mnz, s));
        mxz = fmaxf(mxz, __shfl_xor_sync(FULLM, mxz, s));
    }
    if ((threadIdx.x & 31) == 0) {
        atomicMin(&g_bbmin[0], fenc(mnx));
        atomicMax(&g_bbmax[0], fenc(mxx));
        atomicMin(&g_bbmin[1], fenc(mny));
        atomicMax(&g_bbmax[1], fenc(mxy));
        atomicMin(&g_bbmin[2], fenc(mnz));
        atomicMax(&g_bbmax[2], fenc(mxz));
    }
}

__global__ void __launch_bounds__(256)
grid_count_kernel(const float* __restrict__ p) {
    const int tid = blockIdx.x * 256 + threadIdx.x;
    float bx0 = fdec(g_bbmin[0]), by0 = fdec(g_bbmin[1]), bz0 = fdec(g_bbmin[2]);
    float ivx = (float)GRES / fmaxf(fdec(g_bbmax[0]) - bx0, 1e-9f);
    float ivy = (float)GRES / fmaxf(fdec(g_bbmax[1]) - by0, 1e-9f);
    float ivz = (float)GRES / fmaxf(fdec(g_bbmax[2]) - bz0, 1e-9f);
    int cx = cell1(p[3 * tid + 0], bx0, ivx);
    int cy = cell1(p[3 * tid + 1], by0, ivy);
    int cz = cell1(p[3 * tid + 2], bz0, ivz);
    atomicAdd(&g_cellcnt[(cz * GRES + cy) * GRES + cx], 1);
}

__global__ void grid_scan_kernel() {
    __shared__ int sc[1024];
    const int t = threadIdx.x;
    const int b = 4 * t;
    int c0 = g_cellcnt[b + 0], c1 = g_cellcnt[b + 1];
    int c2 = g_cellcnt[b + 2], c3 = g_cellcnt[b + 3];
    int s = c0 + c1 + c2 + c3;
    sc[t] = s;
    __syncthreads();
    for (int off = 1; off < 1024; off <<= 1) {
        int v = (t >= off) ? sc[t - off] : 0;
        __syncthreads();
        sc[t] += v;
        __syncthreads();
    }
    int excl = sc[t] - s;
    g_cellstart[b + 0] = excl; g_cellcur[b + 0] = excl; excl += c0;
    g_cellstart[b + 1] = excl; g_cellcur[b + 1] = excl; excl += c1;
    g_cellstart[b + 2] = excl; g_cellcur[b + 2] = excl; excl += c2;
    g_cellstart[b + 3] = excl; g_cellcur[b + 3] = excl;
}

__global__ void __launch_bounds__(256)
grid_scatter_kernel(const float* __restrict__ p) {
    const int tid = blockIdx.x * 256 + threadIdx.x;
    float bx0 = fdec(g_bbmin[0]), by0 = fdec(g_bbmin[1]), bz0 = fdec(g_bbmin[2]);
    float ivx = (float)GRES / fmaxf(fdec(g_bbmax[0]) - bx0, 1e-9f);
    float ivy = (float)GRES / fmaxf(fdec(g_bbmax[1]) - by0, 1e-9f);
    float ivz = (float)GRES / fmaxf(fdec(g_bbmax[2]) - bz0, 1e-9f);
    float x = p[3 * tid + 0], y = p[3 * tid + 1], z = p[3 * tid + 2];
    int cx = cell1(x, bx0, ivx);
    int cy = cell1(y, by0, ivy);
    int cz = cell1(z, bz0, ivz);
    int pos = atomicAdd(&g_cellcur[(cz * GRES + cy) * GRES + cx], 1);
    g_ps4[pos] = make_float4(x, y, z, fmaf(x, x, fmaf(y, y, z * z)));
    g_pidn[pos] = tid;
}

// ---------------- KNN: grid shells, 1 query per warp, exact ------------------
// Sorted top-16 in lanes 0..15 (ascending), thr = lane15 value, R12 insert
// machinery. Metric = true squared distance. After completing shell r, stop
// when (r*hmin)^2 >= thr (shell r+1 cells cannot contain a closer point).
__global__ void __launch_bounds__(256)
knn_grid_kernel(const float* __restrict__ p) {
    const int lane = threadIdx.x & 31;
    const int warp = threadIdx.x >> 5;
    const int q    = blockIdx.x * 8 + warp;

    const float qx = p[3 * q + 0], qy = p[3 * q + 1], qz = p[3 * q + 2];
    const float qw = fmaf(qx, qx, fmaf(qy, qy, qz * qz));
    const float m2x = -2.0f * qx, m2y = -2.0f * qy, m2z = -2.0f * qz;

    const float bx0 = fdec(g_bbmin[0]), by0 = fdec(g_bbmin[1]), bz0 = fdec(g_bbmin[2]);
    const float sx = fmaxf(fdec(g_bbmax[0]) - bx0, 1e-9f);
    const float sy = fmaxf(fdec(g_bbmax[1]) - by0, 1e-9f);
    const float sz = fmaxf(fdec(g_bbmax[2]) - bz0, 1e-9f);
    const float ivx = (float)GRES / sx, ivy = (float)GRES / sy, ivz = (float)GRES / sz;
    const float hmin = fminf(sx, fminf(sy, sz)) / (float)GRES;

    const int cx = cell1(qx, bx0, ivx);
    const int cy = cell1(qy, by0, ivy);
    const int cz = cell1(qz, bz0, ivz);

    float best_d = FINF;
    int   best_i = 0;
    float thr    = FINF;
    bool  seeded = false;

    for (int r = 0; r < GRES; r++) {
        if (r >= 1) {
            float rb = (float)(r - 1) * hmin;
            if (rb * rb >= thr) break;
        }
        for (int dz = -r; dz <= r; dz++) {
            const int z = cz + dz;
            if (z < 0 || z >= GRES) continue;
            for (int dy = -r; dy <= r; dy++) {
                const int y = cy + dy;
                if (y < 0 || y >= GRES) continue;
                const bool face = (abs(dz) == r) || (abs(dy) == r);
                const int step = (face || r == 0) ? 1 : 2 * r;
                for (int dx = -r; dx <= r; dx += step) {
                    const int x = cx + dx;
                    if (x < 0 || x >= GRES) continue;
                    const int cid = (z * GRES + y) * GRES + x;
                    const int s   = g_cellstart[cid];
                    const int cnt = g_cellcnt[cid];
                    for (int base = 0; base < cnt; base += 32) {
                        const int i = base + lane;
                        const bool vld = i < cnt;
                        float t = FINF;
                        int pid = 0;
                        if (vld) {
                            float4 c = g_ps4[s + i];
                            pid = g_pidn[s + i];
                            t = fmaf(m2x, c.x,
                                fmaf(m2y, c.y,
                                fmaf(m2z, c.z, c.w + qw)));
                        }
                        if (!seeded) {
                            // bitonic sort-32 ascending on (t, pid) = initial top-16
#pragma unroll
                            for (int k = 2; k <= 32; k <<= 1) {
#pragma unroll
                                for (int j = k >> 1; j >= 1; j >>= 1) {
                                    float od = __shfl_xor_sync(FULLM, t, j);
                                    int   oi = __shfl_xor_sync(FULLM, pid, j);
                                    bool lower = (lane & j) == 0;
                                    bool asc   = (lane & k) == 0;
                                    bool take  = (lower == asc) ? (od < t) : (od > t);
                                    if (take) { t = od; pid = oi; }
                                }
                            }
                            best_d = t;
                            best_i = pid;
                            thr = __shfl_sync(FULLM, best_d, 15);
                            seeded = true;
                            continue;
                        }
                        while (true) {
                            unsigned mask = __ballot_sync(FULLM, t < thr);
                            if (!mask) break;
                            const int src = __ffs(mask) - 1;
                            const float dn = __shfl_sync(FULLM, t, src);
                            const int   in_ = __shfl_sync(FULLM, pid, src);
                            if (lane == src) t = FINF;
                            unsigned lt = __ballot_sync(FULLM, best_d < dn);
                            const int rr = __popc(lt & 0xFFFFu);
                            float pd = __shfl_up_sync(FULLM, best_d, 1);
                            int   pi = __shfl_up_sync(FULLM, best_i, 1);
                            if (lane < 16) {
                                if (lane == rr)      { best_d = dn; best_i = in_; }
                                else if (lane > rr)  { best_d = pd; best_i = pi; }
                            }
                            thr = __shfl_sync(FULLM, best_d, 15);
                        }
                    }
                }
            }
        }
    }
    if (lane < KNN) g_idx[q * KNN + lane] = best_i;
}

// ---------------- xq/xk/xv = x @ {Wq,Wk,Wv} ---------------------------------
__global__ void __launch_bounds__(256)
qkv_gemm_kernel(const float* __restrict__ x,
                const float* __restrict__ Wq,
                const float* __restrict__ Wk,
                const float* __restrict__ Wv) {
    __shared__ __align__(16) float Ws[CF * CF];
    __shared__ __align__(16) float xs[CF * CF];
    const float* W = (blockIdx.y == 0) ? Wq : ((blockIdx.y == 1) ? Wk : Wv);
    float* out = (blockIdx.y == 0) ? g_xq : ((blockIdx.y == 1) ? g_xk : g_xv);

    const int row0 = blockIdx.x * 64;
    const int tid  = threadIdx.y * 64 + threadIdx.x;
    for (int f = tid; f < CF * CF; f += 256) {
        Ws[f] = W[f];
        xs[f] = x[row0 * CF + f];
    }
    __syncthreads();

    const int c  = threadIdx.x;
    const int r0 = threadIdx.y * 16;
    float acc[16];
#pragma unroll
    for (int r = 0; r < 16; r++) acc[r] = 0.0f;

    const float4* xsv = reinterpret_cast<const float4*>(xs);
    for (int j4 = 0; j4 < 16; j4++) {
        float w0 = Ws[(4 * j4 + 0) * CF + c];
        float w1 = Ws[(4 * j4 + 1) * CF + c];
        float w2 = Ws[(4 * j4 + 2) * CF + c];
        float w3 = Ws[(4 * j4 + 3) * CF + c];
#pragma unroll
        for (int r = 0; r < 16; r++) {
            float4 xv = xsv[(r0 + r) * 16 + j4];
            acc[r] = fmaf(xv.x, w0, acc[r]);
            acc[r] = fmaf(xv.y, w1, acc[r]);
            acc[r] = fmaf(xv.z, w2, acc[r]);
            acc[r] = fmaf(xv.w, w3, acc[r]);
        }
    }
#pragma unroll
    for (int r = 0; r < 16; r++) out[(row0 + r0 + r) * CF + c] = acc[r];
}

// ---------------- PPF angle helper ------------------------------------------
__device__ __forceinline__ float angle3(float ux, float uy, float uz,
                                        float vx, float vy, float vz) {
    float cx = uy * vz - uz * vy;
    float cy = uz * vx - ux * vz;
    float cz = ux * vy - uy * vx;
    float cn = sqrtf(cx * cx + cy * cy + cz * cz + 1e-9f);
    float dt = ux * vx + uy * vy + uz * vz;
    return atan2f(cn, dt);
}

// ---------------- Fused: PPF -> pe MLP -> attention -> Wo -> LN -> relu ------
// (R14 winner, byte-identical)
__global__ void __launch_bounds__(128, 8)
fused_attn_kernel(const float* __restrict__ p,
                  const float* __restrict__ x,
                  const float* __restrict__ normals,
                  const float* __restrict__ Wo,
                  const float* __restrict__ w1, const float* __restrict__ b1,
                  const float* __restrict__ w2, const float* __restrict__ b2,
                  const float* __restrict__ ln_g, const float* __restrict__ ln_b,
                  float* __restrict__ out) {
    const int t128 = threadIdx.x;
    const int pt   = t128 >> 6;
    const int tid  = t128 & 63;
    const int n    = blockIdx.x * PPB + pt;

    __shared__ int   idx_s[PPB][KNN];
    __shared__ __align__(16) float ppf_s[PPB][KNN][4];
    __shared__ __align__(16) float pe1t[PPB][CF][KNN];
    __shared__ __align__(16) float k_s[PPB][KNN][CF];
    __shared__ __align__(16) float v_s[PPB][KNN][CF];
    __shared__ __align__(16) float q_s[PPB][CF];
    __shared__ __align__(16) float o_s[PPB][CF];
    __shared__ float attn_s[PPB][NH * KNN];
    __shared__ float red_s[4][2];

    if (tid < KNN) idx_s[pt][tid] = g_idx[n * KNN + tid];
    q_s[pt][tid] = g_xq[n * CF + tid];
    __syncthreads();

    {
        const int k     = tid & 15;
        const int which = tid >> 4;
        const int j = idx_s[pt][k];
        float px = p[3 * n], py = p[3 * n + 1], pz = p[3 * n + 2];
        float dx = p[3 * j] - px, dy = p[3 * j + 1] - py, dz = p[3 * j + 2] - pz;
        float ncx = normals[3 * n], ncy = normals[3 * n + 1], ncz = normals[3 * n + 2];
        float nrx = normals[3 * j], nry = normals[3 * j + 1], nrz = normals[3 * j + 2];
        float ux = (which == 1) ? nrx : ncx;
        float uy = (which == 1) ? nry : ncy;
        float uz = (which == 1) ? nrz : ncz;
        float vx = (which == 2) ? nrx : dx;
        float vy = (which == 2) ? nry : dy;
        float vz = (which == 2) ? nrz : dz;
        float a = angle3(ux, uy, uz, vx, vy, vz);
        float dist = sqrtf(fmaf(dx, dx, fmaf(dy, dy, dz * dz)) + 1e-9f);
        ppf_s[pt][k][which] = (which == 3) ? dist : a;
    }
    __syncthreads();

    {
        float w0 = __ldg(&w1[0 * CF + tid]);
        float wa = __ldg(&w1[1 * CF + tid]);
        float wb = __ldg(&w1[2 * CF + tid]);
        float wc = __ldg(&w1[3 * CF + tid]);
        float bb = __ldg(&b1[tid]);
#pragma unroll
        for (int i = 0; i < KNN; i++) {
            const int k = (i + tid) & 15;
            float4 pf = *reinterpret_cast<const float4*>(&ppf_s[pt][k][0]);
            float v = bb;
            v = fmaf(pf.x, w0, v);
            v = fmaf(pf.y, wa, v);
            v = fmaf(pf.z, wb, v);
            v = fmaf(pf.w, wc, v);
            pe1t[pt][tid][k] = fmaxf(v, 0.0f);
        }
    }
    __syncthreads();

    {
        const int wip   = (t128 >> 5) & 1;
        const int l     = t128 & 31;
        const int c0    = 2 * l;
        const int kbase = 8 * wip;

        unsigned long long acc2[2][4];
        {
            float2 bb2 = *reinterpret_cast<const float2*>(&b2[c0]);
            unsigned long long bp0, bp1;
            PACK2(bp0, __float_as_uint(bb2.x), __float_as_uint(bb2.x));
            PACK2(bp1, __float_as_uint(bb2.y), __float_as_uint(bb2.y));
#pragma unroll
            for (int kp = 0; kp < 4; kp++) { acc2[0][kp] = bp0; acc2[1][kp] = bp1; }
        }
#pragma unroll 4
        for (int j = 0; j < CF; j++) {
            const ulonglong2* row =
                reinterpret_cast<const ulonglong2*>(&pe1t[pt][j][kbase]);
            ulonglong2 r0 = row[0];
            ulonglong2 r1 = row[1];
            float2 w = *reinterpret_cast<const float2*>(&w2[j * CF + c0]);
            unsigned long long wp0, wp1;
            PACK2(wp0, __float_as_uint(w.x), __float_as_uint(w.x));
            PACK2(wp1, __float_as_uint(w.y), __float_as_uint(w.y));
            FMA2(acc2[0][0], r0.x, wp0, acc2[0][0]);
            FMA2(acc2[0][1], r0.y, wp0, acc2[0][1]);
            FMA2(acc2[0][2], r1.x, wp0, acc2[0][2]);
            FMA2(acc2[0][3], r1.y, wp0, acc2[0][3]);
            FMA2(acc2[1][0], r0.x, wp1, acc2[1][0]);
            FMA2(acc2[1][1], r0.y, wp1, acc2[1][1]);
            FMA2(acc2[1][2], r1.x, wp1, acc2[1][2]);
            FMA2(acc2[1][3], r1.y, wp1, acc2[1][3]);
        }
#pragma unroll
        for (int kp = 0; kp < 4; kp++) {
            unsigned lo0, hi0, lo1, hi1;
            UNPACK2(lo0, hi0, acc2[0][kp]);
            UNPACK2(lo1, hi1, acc2[1][kp]);
            const int k0 = kbase + 2 * kp;
            const int k1 = k0 + 1;
            const int j0 = idx_s[pt][k0];
            const int j1 = idx_s[pt][k1];
            float2 gk0 = *reinterpret_cast<const float2*>(&g_xk[j0 * CF + c0]);
            float2 gv0 = *reinterpret_cast<const float2*>(&g_xv[j0 * CF + c0]);
            float2 gk1 = *reinterpret_cast<const float2*>(&g_xk[j1 * CF + c0]);
            float2 gv1 = *reinterpret_cast<const float2*>(&g_xv[j1 * CF + c0]);
            float a0c0 = __uint_as_float(lo0), a1c0 = __uint_as_float(hi0);
            float a0c1 = __uint_as_float(lo1), a1c1 = __uint_as_float(hi1);
            *reinterpret_cast<float2*>(&k_s[pt][k0][c0]) =
                make_float2(gk0.x + a0c0, gk0.y + a0c1);
            *reinterpret_cast<float2*>(&v_s[pt][k0][c0]) =
                make_float2(gv0.x + a0c0, gv0.y + a0c1);
            *reinterpret_cast<float2*>(&k_s[pt][k1][c0]) =
                make_float2(gk1.x + a1c0, gk1.y + a1c1);
            *reinterpret_cast<float2*>(&v_s[pt][k1][c0]) =
                make_float2(gv1.x + a1c0, gv1.y + a1c1);
        }
    }
    __syncthreads();

    {
        const int h  = tid >> 4;
        const int kk = tid & 15;
        float logit = 0.0f;
        const float4* kv = reinterpret_cast<const float4*>(&k_s[pt][kk][h * DHD]);
        const float4* qv = reinterpret_cast<const float4*>(&q_s[pt][h * DHD]);
#pragma unroll
        for (int d4 = 0; d4 < 4; d4++) {
            float4 kq = kv[d4];
            float4 qq = qv[d4];
            logit = fmaf(qq.x, kq.x, logit);
            logit = fmaf(qq.y, kq.y, logit);
            logit = fmaf(qq.z, kq.z, logit);
            logit = fmaf(qq.w, kq.w, logit);
        }
        logit *= 0.25f;

        float m = logit;
#pragma unroll
        for (int s = 8; s >= 1; s >>= 1)
            m = fmaxf(m, __shfl_xor_sync(FULLM, m, s, 16));
        float e = __expf(logit - m);
        float ssum = e;
#pragma unroll
        for (int s = 8; s >= 1; s >>= 1)
            ssum += __shfl_xor_sync(FULLM, ssum, s, 16);
        attn_s[pt][tid] = e / ssum;
    }
    __syncthreads();

    {
        float o = 0.0f;
        const int hb = tid & ~15;
#pragma unroll
        for (int k = 0; k < KNN; k++)
            o = fmaf(attn_s[pt][hb + k], v_s[pt][k][tid], o);
        o_s[pt][tid] = o;
    }
    __syncthreads();

    float y = 0.0f;
    {
        const float4* ov = reinterpret_cast<const float4*>(&o_s[pt][0]);
        for (int j4 = 0; j4 < 16; j4++) {
            float4 o4 = ov[j4];
            y = fmaf(o4.x, __ldg(&Wo[(4 * j4 + 0) * CF + tid]), y);
            y = fmaf(o4.y, __ldg(&Wo[(4 * j4 + 1) * CF + tid]), y);
            y = fmaf(o4.z, __ldg(&Wo[(4 * j4 + 2) * CF + tid]), y);
            y = fmaf(o4.w, __ldg(&Wo[(4 * j4 + 3) * CF + tid]), y);
        }
    }

    float s1 = y, s2 = y * y;
#pragma unroll
    for (int s = 16; s >= 1; s >>= 1) {
        s1 += __shfl_xor_sync(FULLM, s1, s);
        s2 += __shfl_xor_sync(FULLM, s2, s);
    }
    const int wrp = t128 >> 5;
    if ((t128 & 31) == 0) {
        red_s[wrp][0] = s1;
        red_s[wrp][1] = s2;
    }
    __syncthreads();
    float S1 = red_s[2 * pt][0] + red_s[2 * pt + 1][0];
    float S2 = red_s[2 * pt][1] + red_s[2 * pt + 1][1];
    float mu  = S1 * (1.0f / 64.0f);
    float var = S2 * (1.0f / 64.0f) - mu * mu;
    float nrm = (y - mu) * rsqrtf(var + 1e-5f);
    float res = fmaf(nrm, __ldg(&ln_g[tid]), __ldg(&ln_b[tid])) + x[n * CF + tid];
    out[n * CF + tid] = fmaxf(res, 0.0f);
}

// ---------------- launch -----------------------------------------------------
extern "C" void kernel_launch(void* const* d_in, const int* in_sizes, int n_in,
                              void* d_out, int out_size) {
    (void)in_sizes; (void)n_in; (void)out_size;
    const float* p       = (const float*)d_in[0];
    const float* x       = (const float*)d_in[1];
    const float* normals = (const float*)d_in[2];
    const float* Wq      = (const float*)d_in[3];
    const float* Wk      = (const float*)d_in[4];
    const float* Wv      = (const float*)d_in[5];
    const float* Wo      = (const float*)d_in[6];
    const float* w1      = (const float*)d_in[7];
    const float* b1      = (const float*)d_in[8];
    const float* w2      = (const float*)d_in[9];
    const float* b2      = (const float*)d_in[10];
    const float* ln_g    = (const float*)d_in[11];
    const float* ln_b    = (const float*)d_in[12];
    float* out = (float*)d_out;

    grid_init_kernel<<<(GC + 1023) / 1024, 1024>>>();
    bbox_kernel<<<NPTS / 256, 256>>>(p);
    grid_count_kernel<<<NPTS / 256, 256>>>(p);
    grid_scan_kernel<<<1, 1024>>>();
    grid_scatter_kernel<<<NPTS / 256, 256>>>(p);
    knn_grid_kernel<<<NPTS / 8, 256>>>(p);
    qkv_gemm_kernel<<<dim3(NPTS / 64, 3), dim3(64, 4)>>>(x, Wq, Wk, Wv);
    fused_attn_kernel<<<NPTS / PPB, 128>>>(p, x, normals, Wo, w1, b1, w2, b2,
                                           ln_g, ln_b, out);
}

// round 16
// speedup vs baseline: 1.4315x; 1.4315x over previous
#include <cuda_runtime.h>
#include <math.h>

#define NPTS 8192
#define CF   64
#define NH   4
#define KNN  16
#define DHD  16
#define PPB  2

#define GRES 16
#define GC   (GRES * GRES * GRES)

#define FINF 3.402823466e38f
#define FULLM 0xffffffffu

#define PACK2(out, lo, hi) \
    asm("mov.b64 %0, {%1, %2};" : "=l"(out) : "r"(lo), "r"(hi))
#define UNPACK2(lo, hi, in) \
    asm("mov.b64 {%0, %1}, %2;" : "=r"(lo), "=r"(hi) : "l"(in))
#define FMA2(d, a, b, c) \
    asm("fma.rn.f32x2 %0, %1, %2, %3;" : "=l"(d) : "l"(a), "l"(b), "l"(c))

// ---------------- scratch (static device memory; no allocations) -------------
__device__ float g_xq[NPTS * CF];
__device__ float g_xk[NPTS * CF];
__device__ float g_xv[NPTS * CF];
__device__ int   g_idx[NPTS * KNN];

__device__ unsigned g_bbmin[3];
__device__ unsigned g_bbmax[3];
__device__ int      g_cellcnt[GC];
__device__ int      g_cellstart[GC + 1];
__device__ int      g_cellcur[GC];
__device__ __align__(16) float4 g_ps4[NPTS];
__device__ int      g_pidn[NPTS];

// ---------------- float <-> ordered-uint encode for atomic min/max ----------
__device__ __forceinline__ unsigned fenc(float f) {
    unsigned u = __float_as_uint(f);
    return (u & 0x80000000u) ? ~u : (u | 0x80000000u);
}
__device__ __forceinline__ float fdec(unsigned e) {
    unsigned u = (e & 0x80000000u) ? (e & 0x7FFFFFFFu) : ~e;
    return __uint_as_float(u);
}
__device__ __forceinline__ int cell1(float v, float lo, float inv) {
    int c = (int)((v - lo) * inv);
    return min(GRES - 1, max(0, c));
}

// ---------------- grid build ------------------------------------------------
__global__ void grid_init_kernel() {
    const int idx = blockIdx.x * 1024 + threadIdx.x;
    if (idx < GC) g_cellcnt[idx] = 0;
    if (blockIdx.x == 0 && threadIdx.x < 3) {
        g_bbmin[threadIdx.x] = 0xFFFFFFFFu;
        g_bbmax[threadIdx.x] = 0u;
    }
}

__global__ void __launch_bounds__(256)
bbox_kernel(const float* __restrict__ p) {
    const int tid = blockIdx.x * 256 + threadIdx.x;
    float x = p[3 * tid + 0], y = p[3 * tid + 1], z = p[3 * tid + 2];
    float mnx = x, mxx = x, mny = y, mxy = y, mnz = z, mxz = z;
#pragma unroll
    for (int s = 16; s >= 1; s >>= 1) {
        mnx = fminf(mnx, __shfl_xor_sync(FULLM, mnx, s));
        mxx = fmaxf(mxx, __shfl_xor_sync(FULLM, mxx, s));
        mny = fminf(mny, __shfl_xor_sync(FULLM, mny, s));
        mxy = fmaxf(mxy, __shfl_xor_sync(FULLM, mxy, s));
        mnz = fminf(mnz, __shfl_xor_sync(FULLM, mnz, s));
        mxz = fmaxf(mxz, __shfl_xor_sync(FULLM, mxz, s));
    }
    if ((threadIdx.x & 31) == 0) {
        atomicMin(&g_bbmin[0], fenc(mnx));
        atomicMax(&g_bbmax[0], fenc(mxx));
        atomicMin(&g_bbmin[1], fenc(mny));
        atomicMax(&g_bbmax[1], fenc(mxy));
        atomicMin(&g_bbmin[2], fenc(mnz));
        atomicMax(&g_bbmax[2], fenc(mxz));
    }
}

__global__ void __launch_bounds__(256)
grid_count_kernel(const float* __restrict__ p) {
    const int tid = blockIdx.x * 256 + threadIdx.x;
    float bx0 = fdec(g_bbmin[0]), by0 = fdec(g_bbmin[1]), bz0 = fdec(g_bbmin[2]);
    float ivx = (float)GRES / fmaxf(fdec(g_bbmax[0]) - bx0, 1e-9f);
    float ivy = (float)GRES / fmaxf(fdec(g_bbmax[1]) - by0, 1e-9f);
    float ivz = (float)GRES / fmaxf(fdec(g_bbmax[2]) - bz0, 1e-9f);
    int cx = cell1(p[3 * tid + 0], bx0, ivx);
    int cy = cell1(p[3 * tid + 1], by0, ivy);
    int cz = cell1(p[3 * tid + 2], bz0, ivz);
    atomicAdd(&g_cellcnt[(cz * GRES + cy) * GRES + cx], 1);
}

// warp-shfl 3-barrier scan over 4096 cells (4/thread)
__global__ void grid_scan_kernel() {
    __shared__ int warp_sums[32];
    const int t    = threadIdx.x;
    const int lane = t & 31;
    const int wid  = t >> 5;
    const int b    = 4 * t;
    int c0 = g_cellcnt[b + 0], c1 = g_cellcnt[b + 1];
    int c2 = g_cellcnt[b + 2], c3 = g_cellcnt[b + 3];
    int s = c0 + c1 + c2 + c3;
    int incl = s;
#pragma unroll
    for (int off = 1; off < 32; off <<= 1) {
        int v = __shfl_up_sync(FULLM, incl, off);
        if (lane >= off) incl += v;
    }
    if (lane == 31) warp_sums[wid] = incl;
    __syncthreads();
    if (wid == 0) {
        int v = warp_sums[lane];
        int inc2 = v;
#pragma unroll
        for (int off = 1; off < 32; off <<= 1) {
            int u = __shfl_up_sync(FULLM, inc2, off);
            if (lane >= off) inc2 += u;
        }
        warp_sums[lane] = inc2 - v;   // exclusive warp offsets
    }
    __syncthreads();
    int excl = incl - s + warp_sums[wid];
    g_cellstart[b + 0] = excl; g_cellcur[b + 0] = excl; excl += c0;
    g_cellstart[b + 1] = excl; g_cellcur[b + 1] = excl; excl += c1;
    g_cellstart[b + 2] = excl; g_cellcur[b + 2] = excl; excl += c2;
    g_cellstart[b + 3] = excl; g_cellcur[b + 3] = excl;
    if (t == 1023) g_cellstart[GC] = NPTS;
}

__global__ void __launch_bounds__(256)
grid_scatter_kernel(const float* __restrict__ p) {
    const int tid = blockIdx.x * 256 + threadIdx.x;
    float bx0 = fdec(g_bbmin[0]), by0 = fdec(g_bbmin[1]), bz0 = fdec(g_bbmin[2]);
    float ivx = (float)GRES / fmaxf(fdec(g_bbmax[0]) - bx0, 1e-9f);
    float ivy = (float)GRES / fmaxf(fdec(g_bbmax[1]) - by0, 1e-9f);
    float ivz = (float)GRES / fmaxf(fdec(g_bbmax[2]) - bz0, 1e-9f);
    float x = p[3 * tid + 0], y = p[3 * tid + 1], z = p[3 * tid + 2];
    int cx = cell1(x, bx0, ivx);
    int cy = cell1(y, by0, ivy);
    int cz = cell1(z, bz0, ivz);
    int pos = atomicAdd(&g_cellcur[(cz * GRES + cy) * GRES + cx], 1);
    g_ps4[pos] = make_float4(x, y, z, fmaf(x, x, fmaf(y, y, z * z)));
    g_pidn[pos] = tid;
}

// ---------------- KNN: grid shells via CONTIGUOUS ROW SEGMENTS ---------------
// One warp per query. Cells consecutive in x are contiguous in g_ps4, so a
// whole row [xlo, xhi] at fixed (y,z) is one range -> full-warp 32-chunks.
// Sorted top-16 in lanes 0..15; R12 insert machinery; exact termination:
// points in shell r are >= (r-1)*hmin away.
__global__ void __launch_bounds__(256)
knn_grid_kernel(const float* __restrict__ p) {
    const int lane = threadIdx.x & 31;
    const int warp = threadIdx.x >> 5;
    const int q    = blockIdx.x * 8 + warp;

    const float qx = p[3 * q + 0], qy = p[3 * q + 1], qz = p[3 * q + 2];
    const float qw = fmaf(qx, qx, fmaf(qy, qy, qz * qz));
    const float m2x = -2.0f * qx, m2y = -2.0f * qy, m2z = -2.0f * qz;

    const float bx0 = fdec(g_bbmin[0]), by0 = fdec(g_bbmin[1]), bz0 = fdec(g_bbmin[2]);
    const float sx = fmaxf(fdec(g_bbmax[0]) - bx0, 1e-9f);
    const float sy = fmaxf(fdec(g_bbmax[1]) - by0, 1e-9f);
    const float sz = fmaxf(fdec(g_bbmax[2]) - bz0, 1e-9f);
    const float ivx = (float)GRES / sx, ivy = (float)GRES / sy, ivz = (float)GRES / sz;
    const float hmin = fminf(sx, fminf(sy, sz)) / (float)GRES;

    const int cx = cell1(qx, bx0, ivx);
    const int cy = cell1(qy, by0, ivy);
    const int cz = cell1(qz, bz0, ivz);

    float best_d = FINF;
    int   best_i = 0;
    float thr    = FINF;
    bool  seeded = false;

    // process one contiguous candidate range [s, e)
    auto process_range = [&](int s, int e) {
        for (int base = s; base < e; base += 32) {
            const int i = base + lane;
            float t = FINF;
            int pid = 0;
            if (i < e) {
                float4 c = g_ps4[i];
                pid = g_pidn[i];
                t = fmaf(m2x, c.x, fmaf(m2y, c.y, fmaf(m2z, c.z, c.w + qw)));
            }
            if (!seeded) {
                // bitonic sort-32 ascending -> initial sorted top-16
#pragma unroll
                for (int k = 2; k <= 32; k <<= 1) {
#pragma unroll
                    for (int j = k >> 1; j >= 1; j >>= 1) {
                        float od = __shfl_xor_sync(FULLM, t, j);
                        int   oi = __shfl_xor_sync(FULLM, pid, j);
                        bool lower = (lane & j) == 0;
                        bool asc   = (lane & k) == 0;
                        bool take  = (lower == asc) ? (od < t) : (od > t);
                        if (take) { t = od; pid = oi; }
                    }
                }
                best_d = t;
                best_i = pid;
                thr = __shfl_sync(FULLM, best_d, 15);
                seeded = true;
                continue;
            }
            while (true) {
                unsigned mask = __ballot_sync(FULLM, t < thr);
                if (!mask) break;
                const int src = __ffs(mask) - 1;
                const float dn = __shfl_sync(FULLM, t, src);
                const int   in_ = __shfl_sync(FULLM, pid, src);
                if (lane == src) t = FINF;
                unsigned lt = __ballot_sync(FULLM, best_d < dn);
                const int rr = __popc(lt & 0xFFFFu);
                float pd = __shfl_up_sync(FULLM, best_d, 1);
                int   pi = __shfl_up_sync(FULLM, best_i, 1);
                if (lane < 16) {
                    if (lane == rr)      { best_d = dn; best_i = in_; }
                    else if (lane > rr)  { best_d = pd; best_i = pi; }
                }
                thr = __shfl_sync(FULLM, best_d, 15);
            }
        }
    };

    // process row [xlo, xhi] at (y, z): one contiguous range
    auto row = [&](int z, int y, int xlo, int xhi) {
        if (y < 0 || y >= GRES) return;
        xlo = max(0, xlo);
        xhi = min(GRES - 1, xhi);
        if (xlo > xhi) return;
        const int cid = (z * GRES + y) * GRES + xlo;
        process_range(g_cellstart[cid], g_cellstart[cid + (xhi - xlo) + 1]);
    };

    for (int r = 0; r < GRES; r++) {
        if (r >= 1) {
            float rb = (float)(r - 1) * hmin;
            if (rb * rb >= thr) break;
        }
        if (r == 0) {
            row(cz, cy, cx, cx);
            continue;
        }
        for (int dz = -r; dz <= r; dz++) {
            const int z = cz + dz;
            if (z < 0 || z >= GRES) continue;
            if (abs(dz) == r) {
                for (int dy = -r; dy <= r; dy++)
                    row(z, cy + dy, cx - r, cx + r);
            } else {
                row(z, cy - r, cx - r, cx + r);
                row(z, cy + r, cx - r, cx + r);
                for (int dy = -r + 1; dy <= r - 1; dy++) {
                    const int y = cy + dy;
                    if (y < 0 || y >= GRES) continue;
                    row(z, y, cx - r, cx - r);
                    row(z, y, cx + r, cx + r);
                }
            }
        }
    }
    if (lane < KNN) g_idx[q * KNN + lane] = best_i;
}

// ---------------- xq/xk/xv = x @ {Wq,Wk,Wv} ---------------------------------
__global__ void __launch_bounds__(256)
qkv_gemm_kernel(const float* __restrict__ x,
                const float* __restrict__ Wq,
                const float* __restrict__ Wk,
                const float* __restrict__ Wv) {
    __shared__ __align__(16) float Ws[CF * CF];
    __shared__ __align__(16) float xs[CF * CF];
    const float* W = (blockIdx.y == 0) ? Wq : ((blockIdx.y == 1) ? Wk : Wv);
    float* out = (blockIdx.y == 0) ? g_xq : ((blockIdx.y == 1) ? g_xk : g_xv);

    const int row0 = blockIdx.x * 64;
    const int tid  = threadIdx.y * 64 + threadIdx.x;
    for (int f = tid; f < CF * CF; f += 256) {
        Ws[f] = W[f];
        xs[f] = x[row0 * CF + f];
    }
    __syncthreads();

    const int c  = threadIdx.x;
    const int r0 = threadIdx.y * 16;
    float acc[16];
#pragma unroll
    for (int r = 0; r < 16; r++) acc[r] = 0.0f;

    const float4* xsv = reinterpret_cast<const float4*>(xs);
    for (int j4 = 0; j4 < 16; j4++) {
        float w0 = Ws[(4 * j4 + 0) * CF + c];
        float w1 = Ws[(4 * j4 + 1) * CF + c];
        float w2 = Ws[(4 * j4 + 2) * CF + c];
        float w3 = Ws[(4 * j4 + 3) * CF + c];
#pragma unroll
        for (int r = 0; r < 16; r++) {
            float4 xv = xsv[(r0 + r) * 16 + j4];
            acc[r] = fmaf(xv.x, w0, acc[r]);
            acc[r] = fmaf(xv.y, w1, acc[r]);
            acc[r] = fmaf(xv.z, w2, acc[r]);
            acc[r] = fmaf(xv.w, w3, acc[r]);
        }
    }
#pragma unroll
    for (int r = 0; r < 16; r++) out[(row0 + r0 + r) * CF + c] = acc[r];
}

// ---------------- PPF angle helper ------------------------------------------
__device__ __forceinline__ float angle3(float ux, float uy, float uz,
                                        float vx, float vy, float vz) {
    float cx = uy * vz - uz * vy;
    float cy = uz * vx - ux * vz;
    float cz = ux * vy - uy * vx;
    float cn = sqrtf(cx * cx + cy * cy + cz * cz + 1e-9f);
    float dt = ux * vx + uy * vy + uz * vz;
    return atan2f(cn, dt);
}

// ---------------- Fused: PPF -> pe MLP -> attention -> Wo -> LN -> relu ------
// (R14 winner, byte-identical)
__global__ void __launch_bounds__(128, 8)
fused_attn_kernel(const float* __restrict__ p,
                  const float* __restrict__ x,
                  const float* __restrict__ normals,
                  const float* __restrict__ Wo,
                  const float* __restrict__ w1, const float* __restrict__ b1,
                  const float* __restrict__ w2, const float* __restrict__ b2,
                  const float* __restrict__ ln_g, const float* __restrict__ ln_b,
                  float* __restrict__ out) {
    const int t128 = threadIdx.x;
    const int pt   = t128 >> 6;
    const int tid  = t128 & 63;
    const int n    = blockIdx.x * PPB + pt;

    __shared__ int   idx_s[PPB][KNN];
    __shared__ __align__(16) float ppf_s[PPB][KNN][4];
    __shared__ __align__(16) float pe1t[PPB][CF][KNN];
    __shared__ __align__(16) float k_s[PPB][KNN][CF];
    __shared__ __align__(16) float v_s[PPB][KNN][CF];
    __shared__ __align__(16) float q_s[PPB][CF];
    __shared__ __align__(16) float o_s[PPB][CF];
    __shared__ float attn_s[PPB][NH * KNN];
    __shared__ float red_s[4][2];

    if (tid < KNN) idx_s[pt][tid] = g_idx[n * KNN + tid];
    q_s[pt][tid] = g_xq[n * CF + tid];
    __syncthreads();

    {
        const int k     = tid & 15;
        const int which = tid >> 4;
        const int j = idx_s[pt][k];
        float px = p[3 * n], py = p[3 * n + 1], pz = p[3 * n + 2];
        float dx = p[3 * j] - px, dy = p[3 * j + 1] - py, dz = p[3 * j + 2] - pz;
        float ncx = normals[3 * n], ncy = normals[3 * n + 1], ncz = normals[3 * n + 2];
        float nrx = normals[3 * j], nry = normals[3 * j + 1], nrz = normals[3 * j + 2];
        float ux = (which == 1) ? nrx : ncx;
        float uy = (which == 1) ? nry : ncy;
        float uz = (which == 1) ? nrz : ncz;
        float vx = (which == 2) ? nrx : dx;
        float vy = (which == 2) ? nry : dy;
        float vz = (which == 2) ? nrz : dz;
        float a = angle3(ux, uy, uz, vx, vy, vz);
        float dist = sqrtf(fmaf(dx, dx, fmaf(dy, dy, dz * dz)) + 1e-9f);
        ppf_s[pt][k][which] = (which == 3) ? dist : a;
    }
    __syncthreads();

    {
        float w0 = __ldg(&w1[0 * CF + tid]);
        float wa = __ldg(&w1[1 * CF + tid]);
        float wb = __ldg(&w1[2 * CF + tid]);
        float wc = __ldg(&w1[3 * CF + tid]);
        float bb = __ldg(&b1[tid]);
#pragma unroll
        for (int i = 0; i < KNN; i++) {
            const int k = (i + tid) & 15;
            float4 pf = *reinterpret_cast<const float4*>(&ppf_s[pt][k][0]);
            float v = bb;
            v = fmaf(pf.x, w0, v);
            v = fmaf(pf.y, wa, v);
            v = fmaf(pf.z, wb, v);
            v = fmaf(pf.w, wc, v);
            pe1t[pt][tid][k] = fmaxf(v, 0.0f);
        }
    }
    __syncthreads();

    {
        const int wip   = (t128 >> 5) & 1;
        const int l     = t128 & 31;
        const int c0    = 2 * l;
        const int kbase = 8 * wip;

        unsigned long long acc2[2][4];
        {
            float2 bb2 = *reinterpret_cast<const float2*>(&b2[c0]);
            unsigned long long bp0, bp1;
            PACK2(bp0, __float_as_uint(bb2.x), __float_as_uint(bb2.x));
            PACK2(bp1, __float_as_uint(bb2.y), __float_as_uint(bb2.y));
#pragma unroll
            for (int kp = 0; kp < 4; kp++) { acc2[0][kp] = bp0; acc2[1][kp] = bp1; }
        }
#pragma unroll 4
        for (int j = 0; j < CF; j++) {
            const ulonglong2* row =
                reinterpret_cast<const ulonglong2*>(&pe1t[pt][j][kbase]);
            ulonglong2 r0 = row[0];
            ulonglong2 r1 = row[1];
            float2 w = *reinterpret_cast<const float2*>(&w2[j * CF + c0]);
            unsigned long long wp0, wp1;
            PACK2(wp0, __float_as_uint(w.x), __float_as_uint(w.x));
            PACK2(wp1, __float_as_uint(w.y), __float_as_uint(w.y));
            FMA2(acc2[0][0], r0.x, wp0, acc2[0][0]);
            FMA2(acc2[0][1], r0.y, wp0, acc2[0][1]);
            FMA2(acc2[0][2], r1.x, wp0, acc2[0][2]);
            FMA2(acc2[0][3], r1.y, wp0, acc2[0][3]);
            FMA2(acc2[1][0], r0.x, wp1, acc2[1][0]);
            FMA2(acc2[1][1], r0.y, wp1, acc2[1][1]);
            FMA2(acc2[1][2], r1.x, wp1, acc2[1][2]);
            FMA2(acc2[1][3], r1.y, wp1, acc2[1][3]);
        }
#pragma unroll
        for (int kp = 0; kp < 4; kp++) {
            unsigned lo0, hi0, lo1, hi1;
            UNPACK2(lo0, hi0, acc2[0][kp]);
            UNPACK2(lo1, hi1, acc2[1][kp]);
            const int k0 = kbase + 2 * kp;
            const int k1 = k0 + 1;
            const int j0 = idx_s[pt][k0];
            const int j1 = idx_s[pt][k1];
            float2 gk0 = *reinterpret_cast<const float2*>(&g_xk[j0 * CF + c0]);
            float2 gv0 = *reinterpret_cast<const float2*>(&g_xv[j0 * CF + c0]);
            float2 gk1 = *reinterpret_cast<const float2*>(&g_xk[j1 * CF + c0]);
            float2 gv1 = *reinterpret_cast<const float2*>(&g_xv[j1 * CF + c0]);
            float a0c0 = __uint_as_float(lo0), a1c0 = __uint_as_float(hi0);
            float a0c1 = __uint_as_float(lo1), a1c1 = __uint_as_float(hi1);
            *reinterpret_cast<float2*>(&k_s[pt][k0][c0]) =
                make_float2(gk0.x + a0c0, gk0.y + a0c1);
            *reinterpret_cast<float2*>(&v_s[pt][k0][c0]) =
                make_float2(gv0.x + a0c0, gv0.y + a0c1);
            *reinterpret_cast<float2*>(&k_s[pt][k1][c0]) =
                make_float2(gk1.x + a1c0, gk1.y + a1c1);
            *reinterpret_cast<float2*>(&v_s[pt][k1][c0]) =
                make_float2(gv1.x + a1c0, gv1.y + a1c1);
        }
    }
    __syncthreads();

    {
        const int h  = tid >> 4;
        const int kk = tid & 15;
        float logit = 0.0f;
        const float4* kv = reinterpret_cast<const float4*>(&k_s[pt][kk][h * DHD]);
        const float4* qv = reinterpret_cast<const float4*>(&q_s[pt][h * DHD]);
#pragma unroll
        for (int d4 = 0; d4 < 4; d4++) {
            float4 kq = kv[d4];
            float4 qq = qv[d4];
            logit = fmaf(qq.x, kq.x, logit);
            logit = fmaf(qq.y, kq.y, logit);
            logit = fmaf(qq.z, kq.z, logit);
            logit = fmaf(qq.w, kq.w, logit);
        }
        logit *= 0.25f;

        float m = logit;
#pragma unroll
        for (int s = 8; s >= 1; s >>= 1)
            m = fmaxf(m, __shfl_xor_sync(FULLM, m, s, 16));
        float e = __expf(logit - m);
        float ssum = e;
#pragma unroll
        for (int s = 8; s >= 1; s >>= 1)
            ssum += __shfl_xor_sync(FULLM, ssum, s, 16);
        attn_s[pt][tid] = e / ssum;
    }
    __syncthreads();

    {
        float o = 0.0f;
        const int hb = tid & ~15;
#pragma unroll
        for (int k = 0; k < KNN; k++)
            o = fmaf(attn_s[pt][hb + k], v_s[pt][k][tid], o);
        o_s[pt][tid] = o;
    }
    __syncthreads();

    float y = 0.0f;
    {
        const float4* ov = reinterpret_cast<const float4*>(&o_s[pt][0]);
        for (int j4 = 0; j4 < 16; j4++) {
            float4 o4 = ov[j4];
            y = fmaf(o4.x, __ldg(&Wo[(4 * j4 + 0) * CF + tid]), y);
            y = fmaf(o4.y, __ldg(&Wo[(4 * j4 + 1) * CF + tid]), y);
            y = fmaf(o4.z, __ldg(&Wo[(4 * j4 + 2) * CF + tid]), y);
            y = fmaf(o4.w, __ldg(&Wo[(4 * j4 + 3) * CF + tid]), y);
        }
    }

    float s1 = y, s2 = y * y;
#pragma unroll
    for (int s = 16; s >= 1; s >>= 1) {
        s1 += __shfl_xor_sync(FULLM, s1, s);
        s2 += __shfl_xor_sync(FULLM, s2, s);
    }
    const int wrp = t128 >> 5;
    if ((t128 & 31) == 0) {
        red_s[wrp][0] = s1;
        red_s[wrp][1] = s2;
    }
    __syncthreads();
    float S1 = red_s[2 * pt][0] + red_s[2 * pt + 1][0];
    float S2 = red_s[2 * pt][1] + red_s[2 * pt + 1][1];
    float mu  = S1 * (1.0f / 64.0f);
    float var = S2 * (1.0f / 64.0f) - mu * mu;
    float nrm = (y - mu) * rsqrtf(var + 1e-5f);
    float res = fmaf(nrm, __ldg(&ln_g[tid]), __ldg(&ln_b[tid])) + x[n * CF + tid];
    out[n * CF + tid] = fmaxf(res, 0.0f);
}

// ---------------- launch -----------------------------------------------------
extern "C" void kernel_launch(void* const* d_in, const int* in_sizes, int n_in,
                              void* d_out, int out_size) {
    (void)in_sizes; (void)n_in; (void)out_size;
    const float* p       = (const float*)d_in[0];
    const float* x       = (const float*)d_in[1];
    const float* normals = (const float*)d_in[2];
    const float* Wq      = (const float*)d_in[3];
    const float* Wk      = (const float*)d_in[4];
    const float* Wv      = (const float*)d_in[5];
    const float* Wo      = (const float*)d_in[6];
    const float* w1      = (const float*)d_in[7];
    const float* b1      = (const float*)d_in[8];
    const float* w2      = (const float*)d_in[9];
    const float* b2      = (const float*)d_in[10];
    const float* ln_g    = (const float*)d_in[11];
    const float* ln_b    = (const float*)d_in[12];
    float* out = (float*)d_out;

    grid_init_kernel<<<(GC + 1023) / 1024, 1024>>>();
    bbox_kernel<<<NPTS / 256, 256>>>(p);
    grid_count_kernel<<<NPTS / 256, 256>>>(p);
    grid_scan_kernel<<<1, 1024>>>();
    grid_scatter_kernel<<<NPTS / 256, 256>>>(p);
    knn_grid_kernel<<<NPTS / 8, 256>>>(p);
    qkv_gemm_kernel<<<dim3(NPTS / 64, 3), dim3(64, 4)>>>(x, Wq, Wk, Wv);
    fused_attn_kernel<<<NPTS / PPB, 128>>>(p, x, normals, Wo, w1, b1, w2, b2,
                                           ln_g, ln_b, out);
}